// round 13
// baseline (speedup 1.0000x reference)
#include <cuda_runtime.h>
#include <cuda_fp16.h>
#include <math.h>
#include <stdint.h>

#define NN 50000
#define EE 300000
#define IND 128
#define HFD 64
#define AHD 4
#define RRD 3
#define HD 256          // HF*AH
#define RN (RRD*NN)
#define RE (RRD*EE)
#define NB ((RN+1023)/1024)   // scan blocks = 147

#define G1X ((NN+127)/128)            // 391
#define G1BLKS (G1X*2*RRD)            // 2346 GEMM1 tiles
#define SCATB ((RE+255)/256)          // 3516 scatter blocks
#define FUSET (1174*5)                // fused grid (guarded)

// ---------------- scratch (device globals; no allocation) ----------------
__device__ __align__(16) __half g_hw16[(size_t)RRD*NN*HD];      // 76.8 MB fp16
__device__ __align__(16) __half g_hhi[(size_t)NN*IND];          // h fp16
__device__ __align__(16) __half g_a2hi[(size_t)NN*RRD*HD];      // edge-out fp16
__device__ __align__(16) __half g_w1h[RRD*HD*IND];              // wW^T  [R,256,128] fp16
__device__ __align__(16) __half g_w2h[HD*RRD*HD];               // linW^T [256,768] fp16
__device__ __align__(16) float4 g_ew[RE];                       // per-edge sg*exp(alpha), 4 heads
__device__ int   g_counts[RN];
__device__ int   g_rowptr[RN];
__device__ int   g_cursor[RN];
__device__ int   g_srclist[RE];
__device__ __align__(16) float g_P1[NN];
__device__ __align__(16) float g_P2[NN];
__device__ __align__(16) float g_Q1[RN*AHD];
__device__ __align__(16) float g_Q2[RN*AHD];
__device__ __align__(16) float g_u1[IND];
__device__ __align__(16) float g_u2[IND];
__device__ __align__(16) float g_v1[RRD*AHD*IND];
__device__ __align__(16) float g_v2[RRD*AHD*IND];
__device__ float g_cq1[RRD*AHD];
__device__ float g_cq2[RRD*AHD];
__device__ float g_cscore;
__device__ int   g_bsums[256];

// ---------------- helpers ----------------
__device__ __forceinline__ uint32_t smaddr(const void* p) {
    uint32_t a;
    asm("{ .reg .u64 t; cvta.to.shared.u64 t, %1; cvt.u32.u64 %0, t; }" : "=r"(a) : "l"(p));
    return a;
}
__device__ __forceinline__ void cp16(uint32_t d, const void* s, int sz) {
    asm volatile("cp.async.cg.shared.global [%0], [%1], 16, %2;" :: "r"(d), "l"(s), "r"(sz));
}
__device__ __forceinline__ void ldsm4(uint32_t* r, uint32_t addr) {
    asm volatile("ldmatrix.sync.aligned.m8n8.x4.shared.b16 {%0,%1,%2,%3}, [%4];"
                 : "=r"(r[0]), "=r"(r[1]), "=r"(r[2]), "=r"(r[3]) : "r"(addr));
}
__device__ __forceinline__ void mma16816(float* c, const uint32_t* a, uint32_t b0, uint32_t b1) {
    asm volatile("mma.sync.aligned.m16n8k16.row.col.f32.f16.f16.f32 "
                 "{%0,%1,%2,%3}, {%4,%5,%6,%7}, {%8,%9}, {%0,%1,%2,%3};"
                 : "+f"(c[0]), "+f"(c[1]), "+f"(c[2]), "+f"(c[3])
                 : "r"(a[0]), "r"(a[1]), "r"(a[2]), "r"(a[3]), "r"(b0), "r"(b1));
}

// scatter body: CSR slot + per-edge attention weight (unchanged arithmetic)
__device__ __forceinline__ void scatter_body(int t, const int* __restrict__ src,
                                             const int* __restrict__ dst) {
    if (t >= RE) return;
    int r = t / EE;
    int s = src[t], d = dst[t];
    int i = r*NN + d;
    int pos = g_rowptr[i] + g_bsums[i >> 10] + atomicAdd(&g_cursor[i], 1);
    g_srclist[pos] = s;

    float sc = g_P1[s] + g_P2[d] + g_cscore;
    float sg = (sc > 0.f) ? 1.f : ((sc < 0.f) ? -1.f : 0.f);
    float4 q1 = *(const float4*)&g_Q1[(r*NN + s)*AHD];
    float4 q2 = *(const float4*)&g_Q2[i*AHD];
    float a0 = sg*q1.x + q2.x; a0 = (a0 >= 0.f) ? a0 : 0.01f*a0;
    float a1 = sg*q1.y + q2.y; a1 = (a1 >= 0.f) ? a1 : 0.01f*a1;
    float a2 = sg*q1.z + q2.z; a2 = (a2 >= 0.f) ? a2 : 0.01f*a2;
    float a3 = sg*q1.w + q2.w; a3 = (a3 >= 0.f) ? a3 : 0.01f*a3;
    g_ew[pos] = make_float4(sg*expf(a0), sg*expf(a1), sg*expf(a2), sg*expf(a3));
}

// ---------------- fused prep: vecs (13 blk) + transB (2304 blk) + zero (1172 blk)
#define PREP_VECS 13
#define PREP_TB   ((RRD*HD*IND + HD*RRD*HD + 127)/128)   // 2304
#define PREP_ZERO ((RN + 127)/128)                        // 1172
#define PREP_BLOCKS (PREP_VECS + PREP_TB + PREP_ZERO)

__global__ void k_prep(const float* __restrict__ dW, const float* __restrict__ db,
                       const float* __restrict__ fW, const float* __restrict__ fb,
                       const float* __restrict__ wW, const float* __restrict__ wb,
                       const float* __restrict__ aW, const float* __restrict__ ab,
                       const float* __restrict__ linW) {
    int bid = blockIdx.x, i = threadIdx.x;
    if (bid < PREP_VECS) {
        if (bid == 0) {
            float u1 = 0.f, u2 = 0.f;
            for (int j = 0; j < HD; j++) {
                float d  = dW[i*HD + j];
                float f0 = fW[j], f1 = fW[HD + j], f2 = fW[2*HD + j];
                u1 += d * (f0 + f2);
                u2 += d * (f1 - f2);
            }
            g_u1[i] = u1; g_u2[i] = u2;
            if (i == 0) {
                float c = fb[0];
                for (int j = 0; j < HD; j++) c += db[j] * (fW[j] + fW[HD + j]);
                g_cscore = c;
            }
            if (i < RRD*AHD) {
                int r = i / AHD, a = i % AHD;
                const float* wbp = wb + r*HD + a*HFD;
                const float* a1 = aW + r*2*HFD;
                const float* a2 = a1 + HFD;
                float c1 = 0.f, c2 = 0.f;
                for (int k = 0; k < HFD; k++) { c1 += wbp[k]*a1[k]; c2 += wbp[k]*a2[k]; }
                g_cq1[i] = c1;
                g_cq2[i] = c2 + ab[r];
            }
        } else {
            int ra = bid - 1;       // 0..11
            int r = ra / AHD, a = ra % AHD;
            const float* a1 = aW + r*2*HFD;
            const float* a2 = a1 + HFD;
            const float* wp = wW + ((size_t)(r*IND + i))*HD + a*HFD;
            float v1 = 0.f, v2 = 0.f;
            for (int k = 0; k < HFD; k++) { v1 += wp[k]*a1[k]; v2 += wp[k]*a2[k]; }
            g_v1[ra*IND + i] = v1;
            g_v2[ra*IND + i] = v2;
        }
    } else if (bid < PREP_VECS + PREP_TB) {
        int t = (bid - PREP_VECS)*128 + i;
        const int W1 = RRD*HD*IND;
        const int W2 = HD*RRD*HD;
        if (t < W1) {
            int r = t / (HD*IND);
            int rem = t % (HD*IND);
            int n = rem / IND, k = rem % IND;
            g_w1h[t] = __float2half_rn(wW[((size_t)r*IND + k)*HD + n]);
        } else if (t < W1 + W2) {
            int t2 = t - W1;
            int n = t2 / (RRD*HD), k = t2 % (RRD*HD);
            g_w2h[t2] = __float2half_rn(linW[(size_t)k*HD + n]);
        }
    } else {
        int t = (bid - PREP_VECS - PREP_TB)*128 + i;
        if (t < RN) { g_counts[t] = 0; g_cursor[t] = 0; }
    }
}

// ---------------- CSR construction ----------------
__global__ void k_hist(const int* __restrict__ dst) {
    int t = blockIdx.x*blockDim.x + threadIdx.x;
    if (t < RE) {
        int r = t / EE;
        atomicAdd(&g_counts[r*NN + dst[t]], 1);
    }
}
__global__ void k_scan1() {
    __shared__ int sm[1024];
    int tid = threadIdx.x;
    int i = blockIdx.x*1024 + tid;
    int v = (i < RN) ? g_counts[i] : 0;
    sm[tid] = v; __syncthreads();
    for (int off = 1; off < 1024; off <<= 1) {
        int t = (tid >= off) ? sm[tid-off] : 0;
        __syncthreads();
        sm[tid] += t; __syncthreads();
    }
    if (i < RN) g_rowptr[i] = sm[tid] - v;
    if (tid == 1023) g_bsums[blockIdx.x] = sm[1023];
}
__global__ void k_scan2() {
    __shared__ int sm[256];
    int tid = threadIdx.x;
    int v = (tid < NB) ? g_bsums[tid] : 0;
    sm[tid] = v; __syncthreads();
    for (int off = 1; off < 256; off <<= 1) {
        int t = (tid >= off) ? sm[tid-off] : 0;
        __syncthreads();
        sm[tid] += t; __syncthreads();
    }
    if (tid < NB) g_bsums[tid] = sm[tid] - v;
}
// rowptr base = g_rowptr[i] + g_bsums[i>>10], applied by consumers.

// ---------------- per-node scalars: batched partials + interleaved reductions ---
__global__ void k_node(const float* __restrict__ h) {
    int warp = threadIdx.x >> 5, lane = threadIdx.x & 31;
    int n = blockIdx.x*8 + warp;
    const float* hp = h + (size_t)n*IND;
    float h0 = hp[lane], h1 = hp[lane+32], h2 = hp[lane+64], h3 = hp[lane+96];
    __half* hh = g_hhi + (size_t)n*IND;
    hh[lane]      = __float2half_rn(h0);
    hh[lane + 32] = __float2half_rn(h1);
    hh[lane + 64] = __float2half_rn(h2);
    hh[lane + 96] = __float2half_rn(h3);

    float part[26];
    part[0] = h0*g_u1[lane] + h1*g_u1[lane+32] + h2*g_u1[lane+64] + h3*g_u1[lane+96];
    part[1] = h0*g_u2[lane] + h1*g_u2[lane+32] + h2*g_u2[lane+64] + h3*g_u2[lane+96];
    #pragma unroll
    for (int ra = 0; ra < 12; ra++) {
        const float* v1 = g_v1 + ra*IND;
        const float* v2 = g_v2 + ra*IND;
        part[2+ra]  = h0*v1[lane] + h1*v1[lane+32] + h2*v1[lane+64] + h3*v1[lane+96];
        part[14+ra] = h0*v2[lane] + h1*v2[lane+32] + h2*v2[lane+64] + h3*v2[lane+96];
    }
    #pragma unroll
    for (int o = 16; o; o >>= 1) {
        #pragma unroll
        for (int k = 0; k < 26; k++)
            part[k] += __shfl_xor_sync(0xffffffffu, part[k], o);
    }
    if (lane == 0) {
        g_P1[n] = part[0];
        g_P2[n] = part[1];
        #pragma unroll
        for (int ra = 0; ra < 12; ra++) {
            int r = ra / AHD, a = ra % AHD;
            g_Q1[(r*NN + n)*AHD + a] = part[2+ra]  + g_cq1[ra];
            g_Q2[(r*NN + n)*AHD + a] = part[14+ra] + g_cq2[ra];
        }
    }
}

// ---------------- 2-stage pipelined mma.sync fp16 GEMM (128x128, K-chunk 64) ---
// fused=1: 1-D grid; 2 of every 5 blocks are GEMM tiles, 3 of 5 are scatter.
#define APAD 72
#define ABUF (128*APAD)
#define BBUF (128*APAD)
#define STAGEE (ABUF + BBUF)

__global__ void __launch_bounds__(256, 2) k_gemm_mma(
    const __half* __restrict__ Ah, const __half* __restrict__ Bh,
    const float* __restrict__ bias, void* __restrict__ Cv,
    int M, int K, int out_fp16, int fused,
    const int* __restrict__ esrc, const int* __restrict__ edst,
    long long strideB, long long strideBias, long long strideC)
{
    extern __shared__ __half sm[];
    int bx, by, bz;
    if (fused) {
        int k = blockIdx.x / 5, r = blockIdx.x % 5;
        if (r >= 2) {
            int s = 3*k + (r - 2);
            if (s < SCATB) scatter_body(s*256 + threadIdx.x, esrc, edst);
            return;
        }
        int gq = 2*k + r;
        if (gq >= G1BLKS) return;
        bx = gq % G1X;
        int rest = gq / G1X;
        by = rest & 1;
        bz = rest >> 1;
    } else {
        bx = blockIdx.x; by = blockIdx.y; bz = blockIdx.z;
    }

    Bh   += (size_t)bz * strideB;
    bias += (size_t)bz * strideBias;
    size_t cbase = (size_t)bz * strideC;

    int tid = threadIdx.x, wid = tid >> 5, lane = tid & 31;
    int g = lane >> 2, tg = lane & 3;
    int row0 = bx * 128, col0 = by * 128;
    int wm = (wid & 3) * 32;
    int wn = (wid >> 2) * 64;

    int rowa = (lane & 7) + ((lane >> 3) & 1) * 8;
    int cola = (lane >> 4) * 8;
    int rowb = (lane & 7) + (lane >> 4) * 8;
    int colb = ((lane >> 3) & 1) * 8;
    uint32_t smb = smaddr(sm);
    uint32_t aoff = ((wm + rowa)*APAD + cola) * 2;
    uint32_t boff = ABUF*2 + ((wn + rowb)*APAD + colb) * 2;

    float acc[2][8][4];
    #pragma unroll
    for (int i = 0; i < 2; i++)
        #pragma unroll
        for (int j = 0; j < 8; j++)
            #pragma unroll
            for (int q = 0; q < 4; q++) acc[i][j][q] = 0.f;

    int nch = K >> 6;

    auto issue = [&](int c, int st) {
        int gk0 = c << 6;
        __half* base = sm + st*STAGEE;
        #pragma unroll
        for (int it = 0; it < 4; it++) {
            int idx = it*256 + tid;
            int rr = idx >> 3, cq = (idx & 7) << 3;
            int gr = row0 + rr;
            int va = (gr < M) ? 16 : 0;
            const __half* pa = (gr < M) ? (Ah + (size_t)gr*K + gk0 + cq) : Ah;
            cp16(smaddr(base + rr*APAD + cq), pa, va);
        }
        #pragma unroll
        for (int it = 0; it < 4; it++) {
            int idx = it*256 + tid;
            int rr = idx >> 3, cq = (idx & 7) << 3;
            size_t gb = (size_t)(col0 + rr)*K + gk0 + cq;
            cp16(smaddr(base + ABUF + rr*APAD + cq), Bh + gb, 16);
        }
        asm volatile("cp.async.commit_group;" ::: "memory");
    };

    issue(0, 0);
    for (int c = 0; c < nch; c++) {
        int st = c & 1;
        if (c + 1 < nch) {
            issue(c + 1, st ^ 1);
            asm volatile("cp.async.wait_group 1;" ::: "memory");
        } else {
            asm volatile("cp.async.wait_group 0;" ::: "memory");
        }
        __syncthreads();

        uint32_t stb = smb + st*(STAGEE*2);
        #pragma unroll
        for (int kb = 0; kb < 4; kb++) {
            uint32_t kbo = kb * 32;
            uint32_t Af[2][4], Bq[4][4];
            ldsm4(Af[0], stb + aoff + kbo);
            ldsm4(Af[1], stb + aoff + 16*APAD*2 + kbo);
            #pragma unroll
            for (int jp = 0; jp < 4; jp++)
                ldsm4(Bq[jp], stb + boff + jp*(16*APAD*2) + kbo);
            #pragma unroll
            for (int j = 0; j < 8; j++) {
                uint32_t b0 = Bq[j >> 1][(j & 1) * 2];
                uint32_t b1 = Bq[j >> 1][(j & 1) * 2 + 1];
                mma16816(acc[0][j], Af[0], b0, b1);
                mma16816(acc[1][j], Af[1], b0, b1);
            }
        }
        __syncthreads();
    }

    #pragma unroll
    for (int i = 0; i < 2; i++) {
        int r0r = row0 + wm + i*16 + g;
        #pragma unroll
        for (int j = 0; j < 8; j++) {
            int cc = col0 + wn + j*8 + tg*2;
            float b0 = bias[cc], b1 = bias[cc+1];
            float v00 = acc[i][j][0] + b0, v01 = acc[i][j][1] + b1;
            float v10 = acc[i][j][2] + b0, v11 = acc[i][j][3] + b1;
            if (out_fp16) {
                __half* Ch = (__half*)Cv;
                if (r0r < M)
                    *(__half2*)(Ch + cbase + (size_t)r0r*HD + cc) =
                        __floats2half2_rn(v00, v01);
                if (r0r + 8 < M)
                    *(__half2*)(Ch + cbase + (size_t)(r0r+8)*HD + cc) =
                        __floats2half2_rn(v10, v11);
            } else {
                float* Cf = (float*)Cv;
                if (r0r < M)
                    *(float2*)(Cf + cbase + (size_t)r0r*HD + cc) = make_float2(v00, v01);
                if (r0r + 8 < M)
                    *(float2*)(Cf + cbase + (size_t)(r0r+8)*HD + cc) = make_float2(v10, v11);
            }
        }
    }
}

// ---------------- edge aggregation: single-pass, 8-deep load batching -----------
__global__ void k_edge() {
    int r = blockIdx.y;
    int warp = threadIdx.x >> 5, lane = threadIdx.x & 31;
    int n = blockIdx.x*8 + warp;
    int idx = r*NN + n;
    float acc[8];
    #pragma unroll
    for (int k = 0; k < 8; k++) acc[k] = 0.f;

    int deg = g_counts[idx];
    if (deg > 0) {
        int base = g_rowptr[idx] + g_bsums[idx >> 10];
        int hl = lane >> 3;
        float dsum = 0.f;

        const __half* hwr = g_hw16 + (size_t)r*NN*HD;
        const int*    sl = g_srclist + base;
        const float4* ew = g_ew + base;
        int co = lane*8;

        auto pick = [&](float4 e) -> float {
            return (hl == 0) ? e.x : (hl == 1) ? e.y : (hl == 2) ? e.z : e.w;
        };
        auto accum = [&](uint4 v, float wh) {
            float2 x0 = __half22float2(*(__half2*)&v.x);
            float2 x1 = __half22float2(*(__half2*)&v.y);
            float2 x2 = __half22float2(*(__half2*)&v.z);
            float2 x3 = __half22float2(*(__half2*)&v.w);
            acc[0] += wh*x0.x; acc[1] += wh*x0.y; acc[2] += wh*x1.x; acc[3] += wh*x1.y;
            acc[4] += wh*x2.x; acc[5] += wh*x2.y; acc[6] += wh*x3.x; acc[7] += wh*x3.y;
        };

        int j = 0;
        for (; j + 8 <= deg; j += 8) {
            int   s0 = sl[j],   s1 = sl[j+1], s2 = sl[j+2], s3 = sl[j+3];
            int   s4 = sl[j+4], s5 = sl[j+5], s6 = sl[j+6], s7 = sl[j+7];
            float w0 = pick(ew[j]),   w1 = pick(ew[j+1]);
            float w2 = pick(ew[j+2]), w3 = pick(ew[j+3]);
            float w4 = pick(ew[j+4]), w5 = pick(ew[j+5]);
            float w6 = pick(ew[j+6]), w7 = pick(ew[j+7]);
            uint4 v0 = *(const uint4*)(hwr + (size_t)s0*HD + co);
            uint4 v1 = *(const uint4*)(hwr + (size_t)s1*HD + co);
            uint4 v2 = *(const uint4*)(hwr + (size_t)s2*HD + co);
            uint4 v3 = *(const uint4*)(hwr + (size_t)s3*HD + co);
            uint4 v4 = *(const uint4*)(hwr + (size_t)s4*HD + co);
            uint4 v5 = *(const uint4*)(hwr + (size_t)s5*HD + co);
            uint4 v6 = *(const uint4*)(hwr + (size_t)s6*HD + co);
            uint4 v7 = *(const uint4*)(hwr + (size_t)s7*HD + co);
            // same op order as two consecutive 4-groups (bit-identical)
            dsum += fabsf(w0) + fabsf(w1) + fabsf(w2) + fabsf(w3);
            accum(v0, w0); accum(v1, w1); accum(v2, w2); accum(v3, w3);
            dsum += fabsf(w4) + fabsf(w5) + fabsf(w6) + fabsf(w7);
            accum(v4, w4); accum(v5, w5); accum(v6, w6); accum(v7, w7);
        }
        for (; j + 4 <= deg; j += 4) {
            int s0 = sl[j], s1 = sl[j+1], s2 = sl[j+2], s3 = sl[j+3];
            float w0 = pick(ew[j]),   w1 = pick(ew[j+1]);
            float w2 = pick(ew[j+2]), w3 = pick(ew[j+3]);
            uint4 v0 = *(const uint4*)(hwr + (size_t)s0*HD + co);
            uint4 v1 = *(const uint4*)(hwr + (size_t)s1*HD + co);
            uint4 v2 = *(const uint4*)(hwr + (size_t)s2*HD + co);
            uint4 v3 = *(const uint4*)(hwr + (size_t)s3*HD + co);
            dsum += fabsf(w0) + fabsf(w1) + fabsf(w2) + fabsf(w3);
            accum(v0, w0); accum(v1, w1); accum(v2, w2); accum(v3, w3);
        }
        for (; j < deg; j++) {
            int s0 = sl[j];
            float w0 = pick(ew[j]);
            uint4 v0 = *(const uint4*)(hwr + (size_t)s0*HD + co);
            dsum += fabsf(w0);
            accum(v0, w0);
        }
        float inv = 1.f / dsum;
        #pragma unroll
        for (int k = 0; k < 8; k++) acc[k] *= inv;
    }
    __half hi[8];
    #pragma unroll
    for (int k = 0; k < 8; k++) hi[k] = __float2half_rn(acc[k]);
    size_t ofs = (size_t)n*(RRD*HD) + r*HD + lane*8;
    *(uint4*)(g_a2hi + ofs) = *(uint4*)hi;
}

// ---------------- launch ----------------
extern "C" void kernel_launch(void* const* d_in, const int* in_sizes, int n_in,
                              void* d_out, int out_size) {
    const float* h    = (const float*)d_in[0];
    const float* dW   = (const float*)d_in[1];
    const float* db   = (const float*)d_in[2];
    const float* fW   = (const float*)d_in[3];
    const float* fb   = (const float*)d_in[4];
    const float* wW   = (const float*)d_in[5];
    const float* wb   = (const float*)d_in[6];
    const float* aW   = (const float*)d_in[7];
    const float* ab   = (const float*)d_in[8];
    const float* linW = (const float*)d_in[9];
    const float* linb = (const float*)d_in[10];
    const int*   src  = (const int*)d_in[11];
    const int*   dst  = (const int*)d_in[12];

    __half *hw16, *hhi, *a2hi, *w1h, *w2h;
    cudaGetSymbolAddress((void**)&hw16, g_hw16);
    cudaGetSymbolAddress((void**)&hhi,  g_hhi);
    cudaGetSymbolAddress((void**)&a2hi, g_a2hi);
    cudaGetSymbolAddress((void**)&w1h,  g_w1h);
    cudaGetSymbolAddress((void**)&w2h,  g_w2h);

    const int smem_bytes = 2*STAGEE*sizeof(__half);   // 73728
    cudaFuncSetAttribute(k_gemm_mma, cudaFuncAttributeMaxDynamicSharedMemorySize, smem_bytes);

    k_prep<<<PREP_BLOCKS, 128>>>(dW, db, fW, fb, wW, wb, aW, ab, linW);   // 0
    k_node<<<NN/8, 256>>>(h);                                             // 1
    k_hist<<<(RE + 255)/256, 256>>>(dst);                                 // 2
    k_scan1<<<NB, 1024>>>();                                              // 3
    k_scan2<<<1, 256>>>();                                                // 4

    // Fused GEMM1 (hw[r] = h @ wW[r] + wb[r] -> fp16) + edge scatter/weights
    k_gemm_mma<<<FUSET, 256, smem_bytes>>>(hhi, w1h, wb, hw16,            // 5
                                           NN, IND, 1, 1, src, dst,
                                           (long long)HD*IND, (long long)HD,
                                           (long long)NN*HD);

    dim3 g2(NN/8, RRD);
    k_edge<<<g2, 256>>>();                                                // 6

    // GEMM2: out = a2 @ linW + linb -> fp32 (M=50000, K=768, N=256)
    dim3 g3(G1X, HD/128, 1);
    k_gemm_mma<<<g3, 256, smem_bytes>>>(a2hi, w2h, linb, d_out,           // 7
                                        NN, RRD*HD, 0, 0, nullptr, nullptr,
                                        0, 0, 0);
}